// round 15
// baseline (speedup 1.0000x reference)
#include <cuda_runtime.h>
#include <cuda_fp16.h>
#include <math.h>
#include <stdint.h>

#define B_   4
#define N_   1536
#define C_   512
#define H_   8
#define D_   64
#define HID_ 1024
#define BN_  (B_*N_)    // 6144
#define BH_  (B_*H_)    // 32
#define EPS_ 1e-5f
#define LOG2E 1.4426950408889634f
#define SOFF  8.0f      // log2-domain softmax offset

// ---------------- scratch ----------------
__device__ __half g_h   [BN_*C_];
__device__ __half g_qkv [BN_*3*C_];
__device__ float  g_x2  [BN_*C_];
__device__ __half g_m1  [BN_*HID_];
__device__ __half g_w1  [C_*3*C_];
__device__ __half g_w2  [C_*HID_];
__device__ __half g_w3  [HID_*C_];

// ---------------- asm helpers ----------------
#define LDSM4(d0,d1,d2,d3,addr) \
    asm volatile("ldmatrix.sync.aligned.m8n8.x4.shared.b16 {%0,%1,%2,%3}, [%4];" \
        : "=r"(d0),"=r"(d1),"=r"(d2),"=r"(d3) : "r"(addr))
#define LDSM4T(d0,d1,d2,d3,addr) \
    asm volatile("ldmatrix.sync.aligned.m8n8.x4.trans.shared.b16 {%0,%1,%2,%3}, [%4];" \
        : "=r"(d0),"=r"(d1),"=r"(d2),"=r"(d3) : "r"(addr))

__device__ __forceinline__ void mma_f16(float c[4], uint32_t a0, uint32_t a1,
                                        uint32_t a2, uint32_t a3,
                                        uint32_t b0, uint32_t b1) {
    asm volatile(
        "mma.sync.aligned.m16n8k16.row.col.f32.f16.f16.f32 "
        "{%0,%1,%2,%3}, {%4,%5,%6,%7}, {%8,%9}, {%0,%1,%2,%3};"
        : "+f"(c[0]), "+f"(c[1]), "+f"(c[2]), "+f"(c[3])
        : "r"(a0), "r"(a1), "r"(a2), "r"(a3), "r"(b0), "r"(b1));
}
__device__ __forceinline__ uint32_t packh2(float lo, float hi) {
    __half2 h = __float22half2_rn(make_float2(lo, hi));
    return *(uint32_t*)&h;
}
__device__ __forceinline__ uint32_t ex2h2(uint32_t x) {
    uint32_t y; asm("ex2.approx.f16x2 %0, %1;" : "=r"(y) : "r"(x)); return y;
}
__device__ __forceinline__ uint32_t smem_u32(const void* p) {
    return (uint32_t)__cvta_generic_to_shared(p);
}
__device__ __forceinline__ void cp16(uint32_t dst, const void* src) {
    asm volatile("cp.async.cg.shared.global [%0], [%1], 16;" :: "r"(dst), "l"(src));
}

// ---------------- mbarrier helpers ----------------
#define MBAR_INIT(addr, cnt) \
    asm volatile("mbarrier.init.shared.b64 [%0], %1;" :: "r"(addr), "r"((uint32_t)(cnt)) : "memory")
#define MBAR_ARRIVE(addr) \
    asm volatile("mbarrier.arrive.shared.b64 _, [%0];" :: "r"(addr) : "memory")
// .noinc: arrival counts against the init expected count
#define CPASYNC_MBAR_ARRIVE(addr) \
    asm volatile("cp.async.mbarrier.arrive.noinc.shared.b64 [%0];" :: "r"(addr) : "memory")
#define MBAR_WAIT(mbar, parity) do { \
    uint32_t _mb = (mbar), _p = (uint32_t)(parity), _done; \
    asm volatile("{\n\t.reg .pred p;\n\t" \
        "mbarrier.try_wait.parity.acquire.cta.shared::cta.b64 p, [%1], %2;\n\t" \
        "selp.b32 %0, 1, 0, p;\n\t}" : "=r"(_done) : "r"(_mb), "r"(_p) : "memory"); \
    if (!_done) { \
        asm volatile("{\n\t.reg .pred P1;\n\t" \
            "WL_%=:\n\t" \
            "mbarrier.try_wait.parity.acquire.cta.shared::cta.b64 P1, [%0], %1, 0x989680;\n\t" \
            "@P1 bra.uni WD_%=;\n\tbra.uni WL_%=;\n\tWD_%=:\n\t}" \
            :: "r"(_mb), "r"(_p) : "memory"); \
    } } while (0)

// ================= dense fp16 GEMM: C = epi(A @ B + bias) =================
// 3-stage cp.async ring with free-running mbarrier sync (no __syncthreads in
// main loop): full = 256 noinc cp.async arrivals, empty = 8 warp arrivals.
#define ASTR 40
#define BSTR 136
template<int EPI, int MT>
__global__ __launch_bounds__(256, (MT == 128) ? 2 : 3) void gemm_h(
    const __half* __restrict__ A, int lda,
    const __half* __restrict__ Bw, int ldb,
    void* __restrict__ Cout, int ldc,
    const float* __restrict__ bias,
    const float* __restrict__ resid, int K)
{
    constexpr int MI = MT / 64;
    constexpr int STAGE_H = MT * ASTR + 32 * BSTR;
    constexpr int STAGE_B = STAGE_H * 2;
    extern __shared__ __align__(16) __half dsm[];

    int tid = threadIdx.x, wid = tid >> 5, lane = tid & 31;
    int wm = wid & 3, wn = wid >> 2;
    int m0 = blockIdx.y * MT, n0 = blockIdx.x * 128;

    uint32_t sbase = smem_u32(dsm);
    uint32_t mb_full  = sbase + 3 * STAGE_B;
    uint32_t mb_empty = mb_full + 24;
    if (tid == 0) {
        #pragma unroll
        for (int s = 0; s < 3; s++) {
            MBAR_INIT(mb_full  + s * 8, 256);
            MBAR_INIT(mb_empty + s * 8, 8);
        }
    }
    __syncthreads();   // inits visible before any cp.async arrive

    float acc[MI][8][4];
    #pragma unroll
    for (int i = 0; i < MI; i++)
        #pragma unroll
        for (int j = 0; j < 8; j++)
            #pragma unroll
            for (int q = 0; q < 4; q++) acc[i][j][q] = 0.f;

    int ar = (tid >> 2), ac = (tid & 3);
    int bk = (tid >> 4), bc = (tid & 15);
    const __half* Ag = A + (size_t)(m0 + ar) * lda + ac * 8;
    const __half* Bg = Bw + (size_t)bk * ldb + n0 + bc * 8;

    uint32_t aoff0 = (ar * ASTR + ac * 8) * 2;
    uint32_t aoff1 = ((ar + 64) * ASTR + ac * 8) * 2;
    uint32_t boff0 = (MT * ASTR + bk * BSTR + bc * 8) * 2;
    uint32_t boff1 = (MT * ASTR + (bk + 16) * BSTR + bc * 8) * 2;

    #define G_PROD(kt_, s_) do {                                              \
        const __half* Ag2 = Ag + (kt_) * 32;                                  \
        const __half* Bg2 = Bg + (size_t)(kt_) * 32 * ldb;                    \
        uint32_t sb = sbase + (s_) * STAGE_B;                                 \
        cp16(sb + aoff0, Ag2);                                                \
        if (MT == 128) cp16(sb + aoff1, Ag2 + (size_t)64 * lda);              \
        cp16(sb + boff0, Bg2);                                                \
        cp16(sb + boff1, Bg2 + (size_t)16 * ldb);                             \
        CPASYNC_MBAR_ARRIVE(mb_full + (s_) * 8);                              \
    } while (0)

    int T = K >> 5;
    G_PROD(0, 0);
    G_PROD(1, 1);

    int l15 = lane & 15, lhi = lane >> 4;
    int buf = 0, nbuf = 2;
    int fp = 0;                 // full parity for stage 'buf' at this use
    int e3 = 0, epar = 0;       // empty parity tracker for producer waits
    for (int kt = 0; kt < T; kt++) {
        // produce first (cp.asyncs fly while we spin on full below)
        int pc = kt + 2;
        if (pc < T) {
            if (pc >= 3) MBAR_WAIT(mb_empty + nbuf * 8, epar);
            G_PROD(pc, nbuf);
        }
        MBAR_WAIT(mb_full + buf * 8, fp);

        uint32_t sA = sbase + buf * STAGE_B;
        uint32_t sB = sA + MT * ASTR * 2;
        uint32_t af[MI][2][4];
        #pragma unroll
        for (int i = 0; i < MI; i++) {
            uint32_t base = sA + ((wm * (MT / 4) + i * 16 + l15) * ASTR + lhi * 8) * 2;
            #pragma unroll
            for (int s = 0; s < 2; s++)
                LDSM4(af[i][s][0], af[i][s][1], af[i][s][2], af[i][s][3],
                      base + s * 32);
        }
        #pragma unroll
        for (int s = 0; s < 2; s++) {
            uint32_t bbase = sB + ((s * 16 + l15) * BSTR + wn * 64 + lhi * 8) * 2;
            #pragma unroll
            for (int jj = 0; jj < 4; jj++) {
                uint32_t b0, b1, b2, b3;
                LDSM4T(b0, b1, b2, b3, bbase + jj * 32);
                #pragma unroll
                for (int i = 0; i < MI; i++) {
                    mma_f16(acc[i][2 * jj],     af[i][s][0], af[i][s][1], af[i][s][2], af[i][s][3], b0, b1);
                    mma_f16(acc[i][2 * jj + 1], af[i][s][0], af[i][s][1], af[i][s][2], af[i][s][3], b2, b3);
                }
            }
        }
        if (lane == 0) MBAR_ARRIVE(mb_empty + buf * 8);

        buf++;  if (buf == 3)  { buf = 0; fp ^= 1; }
        nbuf++; if (nbuf == 3) nbuf = 0;
        if (kt >= 1) { e3++; if (e3 == 3) { e3 = 0; epar ^= 1; } }
    }

    int rq = lane >> 2, cq = lane & 3;
    #pragma unroll
    for (int i = 0; i < MI; i++) {
        #pragma unroll
        for (int half = 0; half < 2; half++) {
            size_t r = (size_t)(m0 + wm * (MT / 4) + i * 16 + rq + half * 8);
            #pragma unroll
            for (int j = 0; j < 8; j++) {
                int c = n0 + wn * 64 + j * 8 + 2 * cq;
                float v0 = acc[i][j][half * 2 + 0];
                float v1 = acc[i][j][half * 2 + 1];
                if (EPI == 0) {
                    v0 += bias[c]; v1 += bias[c + 1];
                    *(uint32_t*)((__half*)Cout + r * ldc + c) = packh2(v0, v1);
                } else if (EPI == 1) {
                    v0 += bias[c]; v1 += bias[c + 1];
                    v0 = 0.5f * v0 * (1.0f + erff(v0 * 0.70710678118654752f));
                    v1 = 0.5f * v1 * (1.0f + erff(v1 * 0.70710678118654752f));
                    *(uint32_t*)((__half*)Cout + r * ldc + c) = packh2(v0, v1);
                } else {
                    const float* rr = resid + r * ldc;
                    float2 o;
                    o.x = v0 + bias[c]     + rr[c];
                    o.y = v1 + bias[c + 1] + rr[c + 1];
                    *(float2*)((float*)Cout + r * ldc + c) = o;
                }
            }
        }
    }
}

// ================= fused flash attention (mbarrier free-running ring) ======
#define FSTR 72
#define FSTAGE_B (2 * 32 * FSTR * 2)   // 9216 B per stage (K+V)
struct __align__(16) FlashSmem {
    union {
        __half q[64 * FSTR];           // prologue only (9216 B, = stage 0)
        __half kv[4][2][32 * FSTR];    // [stage][K/V][row] (36864 B)
    };
    unsigned long long mbar[8];        // full[0..3], empty[0..3]
};
__global__ __launch_bounds__(128, 5) void flash_kernel(
    const __half* __restrict__ qkv,
    const float* __restrict__ x, float* __restrict__ x2)
{
    __shared__ FlashSmem fs;

    int tid = threadIdx.x, wid = tid >> 5, lane = tid & 31;
    int bh = blockIdx.y, b = bh >> 3, h = bh & 7;
    int q0 = blockIdx.x * 64;
    int seg = blockIdx.x >> 3;
    int l15 = lane & 15, lhi = lane >> 4;
    int rq = lane >> 2, cq = lane & 3;
    const float ksc = 0.125f * LOG2E;

    uint32_t mb_full  = smem_u32(&fs.mbar[0]);
    uint32_t mb_empty = smem_u32(&fs.mbar[4]);
    if (tid == 0) {
        #pragma unroll
        for (int s = 0; s < 4; s++) {
            MBAR_INIT(mb_full  + s * 8, 128);
            MBAR_INIT(mb_empty + s * 8, 4);
        }
    }

    // ---- Q prologue: load + segment combine + scale -> smem ----
    {
        const __half* qbase = qkv + ((size_t)(b * N_ + q0)) * (3 * C_) + h * D_;
        #pragma unroll
        for (int it = 0; it < 4; it++) {
            int idx = tid + it * 128;
            int row = idx >> 3, c8 = (idx & 7) * 8;
            const __half* p0 = qbase + (size_t)row * (3 * C_) + c8;
            uint4 va = *(const uint4*)p0;
            __half2* ha = (__half2*)&va;
            float2 f[4];
            #pragma unroll
            for (int i = 0; i < 4; i++) f[i] = __half22float2(ha[i]);
            if (seg >= 1) {
                uint4 vb = *(const uint4*)(p0 - (size_t)512 * (3 * C_));
                __half2* hb = (__half2*)&vb;
                #pragma unroll
                for (int i = 0; i < 4; i++) {
                    float2 g2 = __half22float2(hb[i]);
                    f[i].x += 0.5f * g2.x; f[i].y += 0.5f * g2.y;
                }
            }
            if (seg >= 2) {
                uint4 vc = *(const uint4*)(p0 - (size_t)1024 * (3 * C_));
                __half2* hc = (__half2*)&vc;
                #pragma unroll
                for (int i = 0; i < 4; i++) {
                    float2 g2 = __half22float2(hc[i]);
                    f[i].x += 0.25f * g2.x; f[i].y += 0.25f * g2.y;
                }
            }
            uint4 o; uint32_t* op = (uint32_t*)&o;
            #pragma unroll
            for (int i = 0; i < 4; i++) op[i] = packh2(f[i].x * ksc, f[i].y * ksc);
            *(uint4*)&fs.q[row * FSTR + c8] = o;
        }
    }
    __syncthreads();

    uint32_t aq[4][4];
    {
        uint32_t base = smem_u32(&fs.q[0]) + ((wid * 16 + l15) * FSTR + lhi * 8) * 2;
        #pragma unroll
        for (int s = 0; s < 4; s++)
            LDSM4(aq[s][0], aq[s][1], aq[s][2], aq[s][3], base + s * 32);
    }
    __syncthreads();

    float oacc[8][4];
    #pragma unroll
    for (int j = 0; j < 8; j++)
        #pragma unroll
        for (int q = 0; q < 4; q++) oacc[j][q] = 0.f;
    float lacc[4] = {0.f, 0.f, 0.f, 0.f};
    const uint32_t ONES = 0x3C003C00u;

    const __half* qkvb = qkv + (size_t)(b * N_) * (3 * C_) + h * D_;

    uint32_t kvdst[4];
    uint32_t soff[4];
    #pragma unroll
    for (int it = 0; it < 4; it++) {
        int idx = tid + it * 128;
        int tens = idx >> 8;
        int row = (idx >> 3) & 31;
        int c = idx & 7;
        kvdst[it] = smem_u32(&fs.kv[0][tens][row * FSTR + c * 8]);
        soff[it] = row * (3 * C_) + (tens ? 2 * C_ : C_) + c * 8;
    }

    #define KV_PROD(pc_, st_) do {                                            \
        const __half* _s = qkvb + (size_t)(pc_) * 32 * (3 * C_);              \
        uint32_t _sb = (uint32_t)(st_) * FSTAGE_B;                            \
        _Pragma("unroll")                                                     \
        for (int it = 0; it < 4; it++)                                        \
            cp16(kvdst[it] + _sb, _s + soff[it]);                             \
        CPASYNC_MBAR_ARRIVE(mb_full + (st_) * 8);                             \
    } while (0)

    KV_PROD(0, 0);
    KV_PROD(1, 1);

    uint32_t kb0 = smem_u32(&fs.kv[0][0][0])
        + ((((lane >> 4) & 1) * 8 + (lane & 7)) * FSTR + ((lane >> 3) & 1) * 8) * 2;
    uint32_t vb0 = smem_u32(&fs.kv[0][1][0]) + (l15 * FSTR + lhi * 8) * 2;

    for (int kc = 0; kc < 48; kc++) {
        int st = kc & 3;

        // produce first (cp.asyncs fly while we spin on full below)
        int pc = kc + 2;
        if (pc < 48) {
            int ps = pc & 3;
            if (pc >= 4) MBAR_WAIT(mb_empty + ps * 8, ((pc - 4) >> 2) & 1);
            KV_PROD(pc, ps);
        }
        MBAR_WAIT(mb_full + st * 8, (kc >> 2) & 1);

        uint32_t kbase = kb0 + st * FSTAGE_B;
        uint32_t vbase = vb0 + st * FSTAGE_B;

        float sacc[4][4];
        #pragma unroll
        for (int j = 0; j < 4; j++)
            #pragma unroll
            for (int q = 0; q < 4; q++) sacc[j][q] = -SOFF;
        #pragma unroll
        for (int s = 0; s < 4; s++) {
            #pragma unroll
            for (int jj = 0; jj < 2; jj++) {
                uint32_t b0, b1, b2, b3;
                LDSM4(b0, b1, b2, b3, kbase + jj * (16 * FSTR * 2) + s * 32);
                mma_f16(sacc[2 * jj],     aq[s][0], aq[s][1], aq[s][2], aq[s][3], b0, b1);
                mma_f16(sacc[2 * jj + 1], aq[s][0], aq[s][1], aq[s][2], aq[s][3], b2, b3);
            }
        }

        uint32_t ph[4][2];
        #pragma unroll
        for (int j = 0; j < 4; j++) {
            ph[j][0] = ex2h2(packh2(sacc[j][0], sacc[j][1]));
            ph[j][1] = ex2h2(packh2(sacc[j][2], sacc[j][3]));
        }

        mma_f16(lacc, ph[0][0], ph[0][1], ph[1][0], ph[1][1], ONES, ONES);
        mma_f16(lacc, ph[2][0], ph[2][1], ph[3][0], ph[3][1], ONES, ONES);

        #pragma unroll
        for (int s = 0; s < 2; s++) {
            #pragma unroll
            for (int jj = 0; jj < 4; jj++) {
                uint32_t b0, b1, b2, b3;
                LDSM4T(b0, b1, b2, b3, vbase + s * (16 * FSTR * 2) + jj * 32);
                mma_f16(oacc[2 * jj],     ph[2 * s][0], ph[2 * s][1], ph[2 * s + 1][0], ph[2 * s + 1][1], b0, b1);
                mma_f16(oacc[2 * jj + 1], ph[2 * s][0], ph[2 * s][1], ph[2 * s + 1][0], ph[2 * s + 1][1], b2, b3);
            }
        }

        if (lane == 0) MBAR_ARRIVE(mb_empty + st * 8);
    }

    float inv[2] = {1.0f / lacc[0], 1.0f / lacc[2]};

    #pragma unroll
    for (int hf = 0; hf < 2; hf++) {
        int row = q0 + wid * 16 + rq + hf * 8;
        size_t base = ((size_t)(b * N_ + row)) * C_ + h * D_;
        #pragma unroll
        for (int j = 0; j < 8; j++) {
            int c = j * 8 + 2 * cq;
            float2 xv = *(const float2*)(x + base + c);
            float2 o;
            o.x = oacc[j][2 * hf]     * inv[hf] + xv.x;
            o.y = oacc[j][2 * hf + 1] * inv[hf] + xv.y;
            *(float2*)(x2 + base + c) = o;
        }
    }
}

// ---------------- LayerNorm: warp per row, shuffle-only ----------------
__global__ __launch_bounds__(256) void ln_kernel(const float* __restrict__ x,
                                                 const float* __restrict__ g,
                                                 const float* __restrict__ b,
                                                 __half* __restrict__ out) {
    int w = threadIdx.x >> 5, lane = threadIdx.x & 31;
    size_t row = (size_t)blockIdx.x * 8 + w;
    const float* xr = x + row * C_;

    float4 v[4];
    float s = 0.f;
    #pragma unroll
    for (int k = 0; k < 4; k++) {
        v[k] = *(const float4*)(xr + (lane + k * 32) * 4);
        s += (v[k].x + v[k].y) + (v[k].z + v[k].w);
    }
    #pragma unroll
    for (int o = 16; o > 0; o >>= 1) s += __shfl_xor_sync(0xffffffffu, s, o);
    float mu = s * (1.0f / C_);

    float t = 0.f;
    #pragma unroll
    for (int k = 0; k < 4; k++) {
        float dx = v[k].x - mu, dy = v[k].y - mu, dz = v[k].z - mu, dw = v[k].w - mu;
        t += dx * dx + dy * dy + dz * dz + dw * dw;
    }
    #pragma unroll
    for (int o = 16; o > 0; o >>= 1) t += __shfl_xor_sync(0xffffffffu, t, o);
    float rstd = rsqrtf(t * (1.0f / C_) + EPS_);

    __half* orow = out + row * C_;
    #pragma unroll
    for (int k = 0; k < 4; k++) {
        int c = (lane + k * 32) * 4;
        float4 gv = *(const float4*)(g + c);
        float4 bv = *(const float4*)(b + c);
        uint2 o;
        o.x = packh2((v[k].x - mu) * rstd * gv.x + bv.x,
                     (v[k].y - mu) * rstd * gv.y + bv.y);
        o.y = packh2((v[k].z - mu) * rstd * gv.z + bv.z,
                     (v[k].w - mu) * rstd * gv.w + bv.w);
        *(uint2*)(orow + c) = o;
    }
}

// ---------------- merged f32 -> f16 weight convert ----------------
#define NW1 (3*C_*C_/4)
#define NW2 (C_*HID_/4)
#define NW3 (HID_*C_/4)
__global__ __launch_bounds__(256) void cvt3_kernel(
    const float* __restrict__ a, const float* __restrict__ bb,
    const float* __restrict__ c,
    __half* __restrict__ wa, __half* __restrict__ wb, __half* __restrict__ wc) {
    int idx = blockIdx.x * 256 + threadIdx.x;
    const float* src; __half* dst; int off;
    if (idx < NW1)            { src = a;  dst = wa; off = idx; }
    else if (idx < NW1 + NW2) { src = bb; dst = wb; off = idx - NW1; }
    else                      { src = c;  dst = wc; off = idx - NW1 - NW2; }
    float4 v = ((const float4*)src)[off];
    uint2 o;
    o.x = packh2(v.x, v.y);
    o.y = packh2(v.z, v.w);
    ((uint2*)dst)[off] = o;
}

// ---------------- launch ----------------
extern "C" void kernel_launch(void* const* d_in, const int* in_sizes, int n_in,
                              void* d_out, int out_size) {
    const float* x      = (const float*)d_in[0];
    const float* ln1_g  = (const float*)d_in[1];
    const float* ln1_b  = (const float*)d_in[2];
    const float* qkv_w  = (const float*)d_in[3];
    const float* qkv_b  = (const float*)d_in[4];
    const float* ln2_g  = (const float*)d_in[5];
    const float* ln2_b  = (const float*)d_in[6];
    const float* fc1_w  = (const float*)d_in[7];
    const float* fc1_b  = (const float*)d_in[8];
    const float* fc2_w  = (const float*)d_in[9];
    const float* fc2_b  = (const float*)d_in[10];
    float* out = (float*)d_out;

    __half *h, *qkv, *m1, *w1, *w2, *w3;
    float *x2;
    cudaGetSymbolAddress((void**)&h,   g_h);
    cudaGetSymbolAddress((void**)&qkv, g_qkv);
    cudaGetSymbolAddress((void**)&x2,  g_x2);
    cudaGetSymbolAddress((void**)&m1,  g_m1);
    cudaGetSymbolAddress((void**)&w1,  g_w1);
    cudaGetSymbolAddress((void**)&w2,  g_w2);
    cudaGetSymbolAddress((void**)&w3,  g_w3);

    constexpr int SMEM128 = 3 * (128 * ASTR + 32 * BSTR) * 2 + 48;
    constexpr int SMEM64  = 3 * (64 * ASTR + 32 * BSTR) * 2 + 48;
    cudaFuncSetAttribute(gemm_h<0, 128>, cudaFuncAttributeMaxDynamicSharedMemorySize, SMEM128);
    cudaFuncSetAttribute(gemm_h<1, 64>,  cudaFuncAttributeMaxDynamicSharedMemorySize, SMEM64);
    cudaFuncSetAttribute(gemm_h<2, 64>,  cudaFuncAttributeMaxDynamicSharedMemorySize, SMEM64);

    cvt3_kernel<<<(NW1 + NW2 + NW3) / 256, 256>>>(qkv_w, fc1_w, fc2_w, w1, w2, w3);
    // 1. LN1 -> h (f16)
    ln_kernel<<<BN_ / 8, 256>>>(x, ln1_g, ln1_b, h);
    // 2. qkv = h @ qkv_w + b
    gemm_h<0, 128><<<dim3(3 * C_ / 128, BN_ / 128), 256, SMEM128>>>(
        h, C_, w1, 3 * C_, qkv, 3 * C_, qkv_b, nullptr, C_);
    // 3-6. fused attention
    flash_kernel<<<dim3(N_ / 64, BH_), 128>>>(qkv, x, x2);
    // 7. LN2 -> h (f16)
    ln_kernel<<<BN_ / 8, 256>>>(x2, ln2_g, ln2_b, h);
    // 8. m1 = gelu(h @ fc1_w + b)   (64-row tiles, 3 CTAs/SM: 0.87 eff waves)
    gemm_h<1, 64><<<dim3(HID_ / 128, BN_ / 64), 256, SMEM64>>>(
        h, C_, w2, HID_, m1, HID_, fc1_b, nullptr, C_);
    // 9. out = x2 + m1 @ fc2_w + b
    gemm_h<2, 64><<<dim3(C_ / 128, BN_ / 64), 256, SMEM64>>>(
        m1, HID_, w3, C_, out, C_, fc2_b, x2, HID_);
}

// round 16
// speedup vs baseline: 1.0347x; 1.0347x over previous
#include <cuda_runtime.h>
#include <cuda_fp16.h>
#include <math.h>
#include <stdint.h>

#define B_   4
#define N_   1536
#define C_   512
#define H_   8
#define D_   64
#define HID_ 1024
#define BN_  (B_*N_)    // 6144
#define BH_  (B_*H_)    // 32
#define EPS_ 1e-5f
#define LOG2E 1.4426950408889634f
#define SOFF  8.0f      // log2-domain softmax offset

// ---------------- scratch ----------------
__device__ __half g_h   [BN_*C_];
__device__ __half g_qkv [BN_*3*C_];
__device__ float  g_x2  [BN_*C_];
__device__ __half g_m1  [BN_*HID_];
__device__ __half g_w1  [C_*3*C_];
__device__ __half g_w2  [C_*HID_];
__device__ __half g_w3  [HID_*C_];

// ---------------- asm helpers ----------------
#define LDSM4(d0,d1,d2,d3,addr) \
    asm volatile("ldmatrix.sync.aligned.m8n8.x4.shared.b16 {%0,%1,%2,%3}, [%4];" \
        : "=r"(d0),"=r"(d1),"=r"(d2),"=r"(d3) : "r"(addr))
#define LDSM4T(d0,d1,d2,d3,addr) \
    asm volatile("ldmatrix.sync.aligned.m8n8.x4.trans.shared.b16 {%0,%1,%2,%3}, [%4];" \
        : "=r"(d0),"=r"(d1),"=r"(d2),"=r"(d3) : "r"(addr))

__device__ __forceinline__ void mma_f16(float c[4], uint32_t a0, uint32_t a1,
                                        uint32_t a2, uint32_t a3,
                                        uint32_t b0, uint32_t b1) {
    asm volatile(
        "mma.sync.aligned.m16n8k16.row.col.f32.f16.f16.f32 "
        "{%0,%1,%2,%3}, {%4,%5,%6,%7}, {%8,%9}, {%0,%1,%2,%3};"
        : "+f"(c[0]), "+f"(c[1]), "+f"(c[2]), "+f"(c[3])
        : "r"(a0), "r"(a1), "r"(a2), "r"(a3), "r"(b0), "r"(b1));
}
__device__ __forceinline__ uint32_t packh2(float lo, float hi) {
    __half2 h = __float22half2_rn(make_float2(lo, hi));
    return *(uint32_t*)&h;
}
__device__ __forceinline__ uint32_t ex2h2(uint32_t x) {
    uint32_t y; asm("ex2.approx.f16x2 %0, %1;" : "=r"(y) : "r"(x)); return y;
}
__device__ __forceinline__ uint32_t smem_u32(const void* p) {
    return (uint32_t)__cvta_generic_to_shared(p);
}
__device__ __forceinline__ void cp16(uint32_t dst, const void* src) {
    asm volatile("cp.async.cg.shared.global [%0], [%1], 16;" :: "r"(dst), "l"(src));
}

// ---------------- mbarrier helpers ----------------
#define MBAR_INIT(addr, cnt) \
    asm volatile("mbarrier.init.shared.b64 [%0], %1;" :: "r"(addr), "r"((uint32_t)(cnt)) : "memory")
#define MBAR_ARRIVE(addr) \
    asm volatile("mbarrier.arrive.shared.b64 _, [%0];" :: "r"(addr) : "memory")
// .noinc: arrival counts against the init expected count
#define CPASYNC_MBAR_ARRIVE(addr) \
    asm volatile("cp.async.mbarrier.arrive.noinc.shared.b64 [%0];" :: "r"(addr) : "memory")
#define MBAR_WAIT(mbar, parity) do { \
    uint32_t _mb = (mbar), _p = (uint32_t)(parity), _done; \
    asm volatile("{\n\t.reg .pred p;\n\t" \
        "mbarrier.try_wait.parity.acquire.cta.shared::cta.b64 p, [%1], %2;\n\t" \
        "selp.b32 %0, 1, 0, p;\n\t}" : "=r"(_done) : "r"(_mb), "r"(_p) : "memory"); \
    if (!_done) { \
        asm volatile("{\n\t.reg .pred P1;\n\t" \
            "WL_%=:\n\t" \
            "mbarrier.try_wait.parity.acquire.cta.shared::cta.b64 P1, [%0], %1, 0x989680;\n\t" \
            "@P1 bra.uni WD_%=;\n\tbra.uni WL_%=;\n\tWD_%=:\n\t}" \
            :: "r"(_mb), "r"(_p) : "memory"); \
    } } while (0)

// ================= dense fp16 GEMM: C = epi(A @ B + bias) =================
// 3-stage cp.async ring with free-running mbarrier sync (no __syncthreads in
// main loop): full = 256 noinc cp.async arrivals, empty = 8 warp arrivals.
#define ASTR 40
#define BSTR 136
template<int EPI, int MT>
__global__ __launch_bounds__(256, (MT == 128) ? 2 : 3) void gemm_h(
    const __half* __restrict__ A, int lda,
    const __half* __restrict__ Bw, int ldb,
    void* __restrict__ Cout, int ldc,
    const float* __restrict__ bias,
    const float* __restrict__ resid, int K)
{
    constexpr int MI = MT / 64;
    constexpr int STAGE_H = MT * ASTR + 32 * BSTR;
    constexpr int STAGE_B = STAGE_H * 2;
    extern __shared__ __align__(16) __half dsm[];

    int tid = threadIdx.x, wid = tid >> 5, lane = tid & 31;
    int wm = wid & 3, wn = wid >> 2;
    int m0 = blockIdx.y * MT, n0 = blockIdx.x * 128;

    uint32_t sbase = smem_u32(dsm);
    uint32_t mb_full  = sbase + 3 * STAGE_B;
    uint32_t mb_empty = mb_full + 24;
    if (tid == 0) {
        #pragma unroll
        for (int s = 0; s < 3; s++) {
            MBAR_INIT(mb_full  + s * 8, 256);
            MBAR_INIT(mb_empty + s * 8, 8);
        }
    }
    __syncthreads();   // inits visible before any cp.async arrive

    float acc[MI][8][4];
    #pragma unroll
    for (int i = 0; i < MI; i++)
        #pragma unroll
        for (int j = 0; j < 8; j++)
            #pragma unroll
            for (int q = 0; q < 4; q++) acc[i][j][q] = 0.f;

    int ar = (tid >> 2), ac = (tid & 3);
    int bk = (tid >> 4), bc = (tid & 15);
    const __half* Ag = A + (size_t)(m0 + ar) * lda + ac * 8;
    const __half* Bg = Bw + (size_t)bk * ldb + n0 + bc * 8;

    uint32_t aoff0 = (ar * ASTR + ac * 8) * 2;
    uint32_t aoff1 = ((ar + 64) * ASTR + ac * 8) * 2;
    uint32_t boff0 = (MT * ASTR + bk * BSTR + bc * 8) * 2;
    uint32_t boff1 = (MT * ASTR + (bk + 16) * BSTR + bc * 8) * 2;

    #define G_PROD(kt_, s_) do {                                              \
        const __half* Ag2 = Ag + (kt_) * 32;                                  \
        const __half* Bg2 = Bg + (size_t)(kt_) * 32 * ldb;                    \
        uint32_t sb = sbase + (s_) * STAGE_B;                                 \
        cp16(sb + aoff0, Ag2);                                                \
        if (MT == 128) cp16(sb + aoff1, Ag2 + (size_t)64 * lda);              \
        cp16(sb + boff0, Bg2);                                                \
        cp16(sb + boff1, Bg2 + (size_t)16 * ldb);                             \
        CPASYNC_MBAR_ARRIVE(mb_full + (s_) * 8);                              \
    } while (0)

    int T = K >> 5;
    G_PROD(0, 0);
    G_PROD(1, 1);

    int l15 = lane & 15, lhi = lane >> 4;
    int buf = 0, nbuf = 2;
    int fp = 0;                 // full parity for stage 'buf' at this use
    int e3 = 0, epar = 0;       // empty parity tracker for producer waits
    for (int kt = 0; kt < T; kt++) {
        // produce first (cp.asyncs fly while we spin on full below)
        int pc = kt + 2;
        if (pc < T) {
            if (pc >= 3) MBAR_WAIT(mb_empty + nbuf * 8, epar);
            G_PROD(pc, nbuf);
        }
        MBAR_WAIT(mb_full + buf * 8, fp);

        uint32_t sA = sbase + buf * STAGE_B;
        uint32_t sB = sA + MT * ASTR * 2;
        uint32_t af[MI][2][4];
        #pragma unroll
        for (int i = 0; i < MI; i++) {
            uint32_t base = sA + ((wm * (MT / 4) + i * 16 + l15) * ASTR + lhi * 8) * 2;
            #pragma unroll
            for (int s = 0; s < 2; s++)
                LDSM4(af[i][s][0], af[i][s][1], af[i][s][2], af[i][s][3],
                      base + s * 32);
        }
        #pragma unroll
        for (int s = 0; s < 2; s++) {
            uint32_t bbase = sB + ((s * 16 + l15) * BSTR + wn * 64 + lhi * 8) * 2;
            #pragma unroll
            for (int jj = 0; jj < 4; jj++) {
                uint32_t b0, b1, b2, b3;
                LDSM4T(b0, b1, b2, b3, bbase + jj * 32);
                #pragma unroll
                for (int i = 0; i < MI; i++) {
                    mma_f16(acc[i][2 * jj],     af[i][s][0], af[i][s][1], af[i][s][2], af[i][s][3], b0, b1);
                    mma_f16(acc[i][2 * jj + 1], af[i][s][0], af[i][s][1], af[i][s][2], af[i][s][3], b2, b3);
                }
            }
        }
        if (lane == 0) MBAR_ARRIVE(mb_empty + buf * 8);

        buf++;  if (buf == 3)  { buf = 0; fp ^= 1; }
        nbuf++; if (nbuf == 3) nbuf = 0;
        if (kt >= 1) { e3++; if (e3 == 3) { e3 = 0; epar ^= 1; } }
    }

    int rq = lane >> 2, cq = lane & 3;
    #pragma unroll
    for (int i = 0; i < MI; i++) {
        #pragma unroll
        for (int half = 0; half < 2; half++) {
            size_t r = (size_t)(m0 + wm * (MT / 4) + i * 16 + rq + half * 8);
            #pragma unroll
            for (int j = 0; j < 8; j++) {
                int c = n0 + wn * 64 + j * 8 + 2 * cq;
                float v0 = acc[i][j][half * 2 + 0];
                float v1 = acc[i][j][half * 2 + 1];
                if (EPI == 0) {
                    v0 += bias[c]; v1 += bias[c + 1];
                    *(uint32_t*)((__half*)Cout + r * ldc + c) = packh2(v0, v1);
                } else if (EPI == 1) {
                    v0 += bias[c]; v1 += bias[c + 1];
                    v0 = 0.5f * v0 * (1.0f + erff(v0 * 0.70710678118654752f));
                    v1 = 0.5f * v1 * (1.0f + erff(v1 * 0.70710678118654752f));
                    *(uint32_t*)((__half*)Cout + r * ldc + c) = packh2(v0, v1);
                } else {
                    const float* rr = resid + r * ldc;
                    float2 o;
                    o.x = v0 + bias[c]     + rr[c];
                    o.y = v1 + bias[c + 1] + rr[c + 1];
                    *(float2*)((float*)Cout + r * ldc + c) = o;
                }
            }
        }
    }
}

// ================= fused flash attention (mbarrier free-running ring) ======
#define FSTR 72
#define FSTAGE_B (2 * 32 * FSTR * 2)   // 9216 B per stage (K+V)
struct __align__(16) FlashSmem {
    union {
        __half q[64 * FSTR];           // prologue only (9216 B, = stage 0)
        __half kv[4][2][32 * FSTR];    // [stage][K/V][row] (36864 B)
    };
    unsigned long long mbar[8];        // full[0..3], empty[0..3]
};
__global__ __launch_bounds__(128, 5) void flash_kernel(
    const __half* __restrict__ qkv,
    const float* __restrict__ x, float* __restrict__ x2)
{
    __shared__ FlashSmem fs;

    int tid = threadIdx.x, wid = tid >> 5, lane = tid & 31;
    int bh = blockIdx.y, b = bh >> 3, h = bh & 7;
    int q0 = blockIdx.x * 64;
    int seg = blockIdx.x >> 3;
    int l15 = lane & 15, lhi = lane >> 4;
    int rq = lane >> 2, cq = lane & 3;
    const float ksc = 0.125f * LOG2E;

    uint32_t mb_full  = smem_u32(&fs.mbar[0]);
    uint32_t mb_empty = smem_u32(&fs.mbar[4]);
    if (tid == 0) {
        #pragma unroll
        for (int s = 0; s < 4; s++) {
            MBAR_INIT(mb_full  + s * 8, 128);
            MBAR_INIT(mb_empty + s * 8, 4);
        }
    }

    // ---- Q prologue: load + segment combine + scale -> smem ----
    {
        const __half* qbase = qkv + ((size_t)(b * N_ + q0)) * (3 * C_) + h * D_;
        #pragma unroll
        for (int it = 0; it < 4; it++) {
            int idx = tid + it * 128;
            int row = idx >> 3, c8 = (idx & 7) * 8;
            const __half* p0 = qbase + (size_t)row * (3 * C_) + c8;
            uint4 va = *(const uint4*)p0;
            __half2* ha = (__half2*)&va;
            float2 f[4];
            #pragma unroll
            for (int i = 0; i < 4; i++) f[i] = __half22float2(ha[i]);
            if (seg >= 1) {
                uint4 vb = *(const uint4*)(p0 - (size_t)512 * (3 * C_));
                __half2* hb = (__half2*)&vb;
                #pragma unroll
                for (int i = 0; i < 4; i++) {
                    float2 g2 = __half22float2(hb[i]);
                    f[i].x += 0.5f * g2.x; f[i].y += 0.5f * g2.y;
                }
            }
            if (seg >= 2) {
                uint4 vc = *(const uint4*)(p0 - (size_t)1024 * (3 * C_));
                __half2* hc = (__half2*)&vc;
                #pragma unroll
                for (int i = 0; i < 4; i++) {
                    float2 g2 = __half22float2(hc[i]);
                    f[i].x += 0.25f * g2.x; f[i].y += 0.25f * g2.y;
                }
            }
            uint4 o; uint32_t* op = (uint32_t*)&o;
            #pragma unroll
            for (int i = 0; i < 4; i++) op[i] = packh2(f[i].x * ksc, f[i].y * ksc);
            *(uint4*)&fs.q[row * FSTR + c8] = o;
        }
    }
    __syncthreads();

    uint32_t aq[4][4];
    {
        uint32_t base = smem_u32(&fs.q[0]) + ((wid * 16 + l15) * FSTR + lhi * 8) * 2;
        #pragma unroll
        for (int s = 0; s < 4; s++)
            LDSM4(aq[s][0], aq[s][1], aq[s][2], aq[s][3], base + s * 32);
    }
    __syncthreads();

    float oacc[8][4];
    #pragma unroll
    for (int j = 0; j < 8; j++)
        #pragma unroll
        for (int q = 0; q < 4; q++) oacc[j][q] = 0.f;
    float lacc[4] = {0.f, 0.f, 0.f, 0.f};
    const uint32_t ONES = 0x3C003C00u;

    const __half* qkvb = qkv + (size_t)(b * N_) * (3 * C_) + h * D_;

    uint32_t kvdst[4];
    uint32_t soff[4];
    #pragma unroll
    for (int it = 0; it < 4; it++) {
        int idx = tid + it * 128;
        int tens = idx >> 8;
        int row = (idx >> 3) & 31;
        int c = idx & 7;
        kvdst[it] = smem_u32(&fs.kv[0][tens][row * FSTR + c * 8]);
        soff[it] = row * (3 * C_) + (tens ? 2 * C_ : C_) + c * 8;
    }

    #define KV_PROD(pc_, st_) do {                                            \
        const __half* _s = qkvb + (size_t)(pc_) * 32 * (3 * C_);              \
        uint32_t _sb = (uint32_t)(st_) * FSTAGE_B;                            \
        _Pragma("unroll")                                                     \
        for (int it = 0; it < 4; it++)                                        \
            cp16(kvdst[it] + _sb, _s + soff[it]);                             \
        CPASYNC_MBAR_ARRIVE(mb_full + (st_) * 8);                             \
    } while (0)

    KV_PROD(0, 0);
    KV_PROD(1, 1);

    uint32_t kb0 = smem_u32(&fs.kv[0][0][0])
        + ((((lane >> 4) & 1) * 8 + (lane & 7)) * FSTR + ((lane >> 3) & 1) * 8) * 2;
    uint32_t vb0 = smem_u32(&fs.kv[0][1][0]) + (l15 * FSTR + lhi * 8) * 2;

    for (int kc = 0; kc < 48; kc++) {
        int st = kc & 3;

        // produce first (cp.asyncs fly while we spin on full below)
        int pc = kc + 2;
        if (pc < 48) {
            int ps = pc & 3;
            if (pc >= 4) MBAR_WAIT(mb_empty + ps * 8, ((pc - 4) >> 2) & 1);
            KV_PROD(pc, ps);
        }
        MBAR_WAIT(mb_full + st * 8, (kc >> 2) & 1);

        uint32_t kbase = kb0 + st * FSTAGE_B;
        uint32_t vbase = vb0 + st * FSTAGE_B;

        float sacc[4][4];
        #pragma unroll
        for (int j = 0; j < 4; j++)
            #pragma unroll
            for (int q = 0; q < 4; q++) sacc[j][q] = -SOFF;
        #pragma unroll
        for (int s = 0; s < 4; s++) {
            #pragma unroll
            for (int jj = 0; jj < 2; jj++) {
                uint32_t b0, b1, b2, b3;
                LDSM4(b0, b1, b2, b3, kbase + jj * (16 * FSTR * 2) + s * 32);
                mma_f16(sacc[2 * jj],     aq[s][0], aq[s][1], aq[s][2], aq[s][3], b0, b1);
                mma_f16(sacc[2 * jj + 1], aq[s][0], aq[s][1], aq[s][2], aq[s][3], b2, b3);
            }
        }

        uint32_t ph[4][2];
        #pragma unroll
        for (int j = 0; j < 4; j++) {
            ph[j][0] = ex2h2(packh2(sacc[j][0], sacc[j][1]));
            ph[j][1] = ex2h2(packh2(sacc[j][2], sacc[j][3]));
        }

        mma_f16(lacc, ph[0][0], ph[0][1], ph[1][0], ph[1][1], ONES, ONES);
        mma_f16(lacc, ph[2][0], ph[2][1], ph[3][0], ph[3][1], ONES, ONES);

        #pragma unroll
        for (int s = 0; s < 2; s++) {
            #pragma unroll
            for (int jj = 0; jj < 4; jj++) {
                uint32_t b0, b1, b2, b3;
                LDSM4T(b0, b1, b2, b3, vbase + s * (16 * FSTR * 2) + jj * 32);
                mma_f16(oacc[2 * jj],     ph[2 * s][0], ph[2 * s][1], ph[2 * s + 1][0], ph[2 * s + 1][1], b0, b1);
                mma_f16(oacc[2 * jj + 1], ph[2 * s][0], ph[2 * s][1], ph[2 * s + 1][0], ph[2 * s + 1][1], b2, b3);
            }
        }

        if (lane == 0) MBAR_ARRIVE(mb_empty + st * 8);
    }

    float inv[2] = {1.0f / lacc[0], 1.0f / lacc[2]};

    #pragma unroll
    for (int hf = 0; hf < 2; hf++) {
        int row = q0 + wid * 16 + rq + hf * 8;
        size_t base = ((size_t)(b * N_ + row)) * C_ + h * D_;
        #pragma unroll
        for (int j = 0; j < 8; j++) {
            int c = j * 8 + 2 * cq;
            float2 xv = *(const float2*)(x + base + c);
            float2 o;
            o.x = oacc[j][2 * hf]     * inv[hf] + xv.x;
            o.y = oacc[j][2 * hf + 1] * inv[hf] + xv.y;
            *(float2*)(x2 + base + c) = o;
        }
    }
}

// ---------------- LayerNorm: warp per row, shuffle-only ----------------
__global__ __launch_bounds__(256) void ln_kernel(const float* __restrict__ x,
                                                 const float* __restrict__ g,
                                                 const float* __restrict__ b,
                                                 __half* __restrict__ out) {
    int w = threadIdx.x >> 5, lane = threadIdx.x & 31;
    size_t row = (size_t)blockIdx.x * 8 + w;
    const float* xr = x + row * C_;

    float4 v[4];
    float s = 0.f;
    #pragma unroll
    for (int k = 0; k < 4; k++) {
        v[k] = *(const float4*)(xr + (lane + k * 32) * 4);
        s += (v[k].x + v[k].y) + (v[k].z + v[k].w);
    }
    #pragma unroll
    for (int o = 16; o > 0; o >>= 1) s += __shfl_xor_sync(0xffffffffu, s, o);
    float mu = s * (1.0f / C_);

    float t = 0.f;
    #pragma unroll
    for (int k = 0; k < 4; k++) {
        float dx = v[k].x - mu, dy = v[k].y - mu, dz = v[k].z - mu, dw = v[k].w - mu;
        t += dx * dx + dy * dy + dz * dz + dw * dw;
    }
    #pragma unroll
    for (int o = 16; o > 0; o >>= 1) t += __shfl_xor_sync(0xffffffffu, t, o);
    float rstd = rsqrtf(t * (1.0f / C_) + EPS_);

    __half* orow = out + row * C_;
    #pragma unroll
    for (int k = 0; k < 4; k++) {
        int c = (lane + k * 32) * 4;
        float4 gv = *(const float4*)(g + c);
        float4 bv = *(const float4*)(b + c);
        uint2 o;
        o.x = packh2((v[k].x - mu) * rstd * gv.x + bv.x,
                     (v[k].y - mu) * rstd * gv.y + bv.y);
        o.y = packh2((v[k].z - mu) * rstd * gv.z + bv.z,
                     (v[k].w - mu) * rstd * gv.w + bv.w);
        *(uint2*)(orow + c) = o;
    }
}

// ---------------- merged f32 -> f16 weight convert ----------------
#define NW1 (3*C_*C_/4)
#define NW2 (C_*HID_/4)
#define NW3 (HID_*C_/4)
__global__ __launch_bounds__(256) void cvt3_kernel(
    const float* __restrict__ a, const float* __restrict__ bb,
    const float* __restrict__ c,
    __half* __restrict__ wa, __half* __restrict__ wb, __half* __restrict__ wc) {
    int idx = blockIdx.x * 256 + threadIdx.x;
    const float* src; __half* dst; int off;
    if (idx < NW1)            { src = a;  dst = wa; off = idx; }
    else if (idx < NW1 + NW2) { src = bb; dst = wb; off = idx - NW1; }
    else                      { src = c;  dst = wc; off = idx - NW1 - NW2; }
    float4 v = ((const float4*)src)[off];
    uint2 o;
    o.x = packh2(v.x, v.y);
    o.y = packh2(v.z, v.w);
    ((uint2*)dst)[off] = o;
}

// ---------------- launch ----------------
extern "C" void kernel_launch(void* const* d_in, const int* in_sizes, int n_in,
                              void* d_out, int out_size) {
    const float* x      = (const float*)d_in[0];
    const float* ln1_g  = (const float*)d_in[1];
    const float* ln1_b  = (const float*)d_in[2];
    const float* qkv_w  = (const float*)d_in[3];
    const float* qkv_b  = (const float*)d_in[4];
    const float* ln2_g  = (const float*)d_in[5];
    const float* ln2_b  = (const float*)d_in[6];
    const float* fc1_w  = (const float*)d_in[7];
    const float* fc1_b  = (const float*)d_in[8];
    const float* fc2_w  = (const float*)d_in[9];
    const float* fc2_b  = (const float*)d_in[10];
    float* out = (float*)d_out;

    __half *h, *qkv, *m1, *w1, *w2, *w3;
    float *x2;
    cudaGetSymbolAddress((void**)&h,   g_h);
    cudaGetSymbolAddress((void**)&qkv, g_qkv);
    cudaGetSymbolAddress((void**)&x2,  g_x2);
    cudaGetSymbolAddress((void**)&m1,  g_m1);
    cudaGetSymbolAddress((void**)&w1,  g_w1);
    cudaGetSymbolAddress((void**)&w2,  g_w2);
    cudaGetSymbolAddress((void**)&w3,  g_w3);

    constexpr int SMEM128 = 3 * (128 * ASTR + 32 * BSTR) * 2 + 48;
    constexpr int SMEM64  = 3 * (64 * ASTR + 32 * BSTR) * 2 + 48;
    cudaFuncSetAttribute(gemm_h<0, 128>, cudaFuncAttributeMaxDynamicSharedMemorySize, SMEM128);
    cudaFuncSetAttribute(gemm_h<1, 128>, cudaFuncAttributeMaxDynamicSharedMemorySize, SMEM128);
    cudaFuncSetAttribute(gemm_h<2, 64>,  cudaFuncAttributeMaxDynamicSharedMemorySize, SMEM64);

    cvt3_kernel<<<(NW1 + NW2 + NW3) / 256, 256>>>(qkv_w, fc1_w, fc2_w, w1, w2, w3);
    // 1. LN1 -> h (f16)
    ln_kernel<<<BN_ / 8, 256>>>(x, ln1_g, ln1_b, h);
    // 2. qkv = h @ qkv_w + b
    gemm_h<0, 128><<<dim3(3 * C_ / 128, BN_ / 128), 256, SMEM128>>>(
        h, C_, w1, 3 * C_, qkv, 3 * C_, qkv_b, nullptr, C_);
    // 3-6. fused attention
    flash_kernel<<<dim3(N_ / 64, BH_), 128>>>(qkv, x, x2);
    // 7. LN2 -> h (f16)
    ln_kernel<<<BN_ / 8, 256>>>(x2, ln2_g, ln2_b, h);
    // 8. m1 = gelu(h @ fc1_w + b)   (MT=128: B-amortization beats wave packing)
    gemm_h<1, 128><<<dim3(HID_ / 128, BN_ / 128), 256, SMEM128>>>(
        h, C_, w2, HID_, m1, HID_, fc1_b, nullptr, C_);
    // 9. out = x2 + m1 @ fc2_w + b  (MT=64: single wave)
    gemm_h<2, 64><<<dim3(C_ / 128, BN_ / 64), 256, SMEM64>>>(
        m1, HID_, w3, C_, out, C_, fc2_b, x2, HID_);
}